// round 2
// baseline (speedup 1.0000x reference)
#include <cuda_runtime.h>
#include <math.h>
#include <stdint.h>

#define NB 8
#define NS 1025
#define NE 1408
#define NH 16
#define ND 88
#define NM (NB*NS)      // 8200

// Scratch (allocation-free rule: __device__ globals)
static __device__ float g_q[(size_t)NM * NE];
static __device__ float g_k[(size_t)NM * NE];
static __device__ float g_v[(size_t)NM * NE];
static __device__ float g_ctx[(size_t)NM * NE];

// ---------------------------------------------------------------------------
// GEMM: C[M,N] = A[M,K] * W[N,K]^T + bias[N]
// 128x128 block, BK=16, 256 threads, 8x8 microtile per thread.
// ---------------------------------------------------------------------------
__global__ __launch_bounds__(256) void gemm_bias_kernel(
    const float* __restrict__ A, const float* __restrict__ W,
    const float* __restrict__ bias, float* __restrict__ C,
    int M, int N, int K)
{
    __shared__ float As[16][132];   // [k][m], padded stride 132 (16B-aligned rows)
    __shared__ float Bs[16][132];   // [k][n]

    const int tid = threadIdx.x;
    const int tx  = tid & 15;
    const int ty  = tid >> 4;
    const int bm  = blockIdx.y * 128;
    const int bn  = blockIdx.x * 128;

    float acc[8][8];
#pragma unroll
    for (int i = 0; i < 8; i++)
#pragma unroll
        for (int j = 0; j < 8; j++) acc[i][j] = 0.f;

    for (int k0 = 0; k0 < K; k0 += 16) {
        // Load A tile + B tile (each 128 rows x 16 k = 512 float4 slots)
#pragma unroll
        for (int it = 0; it < 2; it++) {
            int slot = tid + it * 256;
            int row  = slot >> 2;
            int kc   = (slot & 3) << 2;

            int gr = bm + row;
            float4 av = make_float4(0.f, 0.f, 0.f, 0.f);
            if (gr < M) av = *(const float4*)(A + (size_t)gr * K + k0 + kc);
            As[kc + 0][row] = av.x;
            As[kc + 1][row] = av.y;
            As[kc + 2][row] = av.z;
            As[kc + 3][row] = av.w;

            int gn = bn + row;
            float4 bv = make_float4(0.f, 0.f, 0.f, 0.f);
            if (gn < N) bv = *(const float4*)(W + (size_t)gn * K + k0 + kc);
            Bs[kc + 0][row] = bv.x;
            Bs[kc + 1][row] = bv.y;
            Bs[kc + 2][row] = bv.z;
            Bs[kc + 3][row] = bv.w;
        }
        __syncthreads();

#pragma unroll
        for (int kk = 0; kk < 16; kk++) {
            float a[8], b[8];
            *(float4*)&a[0] = *(const float4*)&As[kk][ty * 8];
            *(float4*)&a[4] = *(const float4*)&As[kk][ty * 8 + 4];
            *(float4*)&b[0] = *(const float4*)&Bs[kk][tx * 8];
            *(float4*)&b[4] = *(const float4*)&Bs[kk][tx * 8 + 4];
#pragma unroll
            for (int i = 0; i < 8; i++)
#pragma unroll
                for (int j = 0; j < 8; j++)
                    acc[i][j] += a[i] * b[j];
        }
        __syncthreads();
    }

    // Epilogue: bias add + store (vectorized)
    const int gc0 = bn + tx * 8;
    float4 bia0 = *(const float4*)(bias + gc0);
    float4 bia1 = *(const float4*)(bias + gc0 + 4);
#pragma unroll
    for (int i = 0; i < 8; i++) {
        int gr = bm + ty * 8 + i;
        if (gr >= M) continue;
        float4 o0, o1;
        o0.x = acc[i][0] + bia0.x; o0.y = acc[i][1] + bia0.y;
        o0.z = acc[i][2] + bia0.z; o0.w = acc[i][3] + bia0.w;
        o1.x = acc[i][4] + bia1.x; o1.y = acc[i][5] + bia1.y;
        o1.z = acc[i][6] + bia1.z; o1.w = acc[i][7] + bia1.w;
        *(float4*)(C + (size_t)gr * N + gc0)     = o0;
        *(float4*)(C + (size_t)gr * N + gc0 + 4) = o1;
    }
}

// ---------------------------------------------------------------------------
// RoPE applied in-place to g_q and g_k.
// x[...,2p], x[...,2p+1] rotated by (cos[s,p], sin[s,p]).
// ---------------------------------------------------------------------------
__global__ void rope_kernel(const float* __restrict__ fcos,
                            const float* __restrict__ fsin)
{
    const int HALF = ND / 2;  // 44
    int idx = blockIdx.x * blockDim.x + threadIdx.x;
    int total = NM * NH * HALF;
    if (idx >= total) return;

    int p = idx % HALF;
    int t = idx / HALF;       // m*NH + h
    int h = t % NH;
    int m = t / NH;
    int s = m % NS;

    float c  = fcos[s * HALF + p];
    float sn = fsin[s * HALF + p];

    size_t base = (size_t)m * NE + h * ND + 2 * p;

    float xr = g_q[base], xi = g_q[base + 1];
    g_q[base]     = xr * c  - xi * sn;
    g_q[base + 1] = xr * sn + xi * c;

    xr = g_k[base]; xi = g_k[base + 1];
    g_k[base]     = xr * c  - xi * sn;
    g_k[base + 1] = xr * sn + xi * c;
}

// ---------------------------------------------------------------------------
// Flash-style attention, fp32.
// grid = (ceil(S/64), H, B), 256 threads (tx 0..15 keys/cols, ty 0..15 queries)
// Each thread: 4 queries x 4 keys for scores; 4 queries x 6 out-cols for PV.
// smem: q_s[88][68] (transposed), k_s[88][68] (transposed),
//       v_s[64][96] (row-major, zero-padded cols), p_s[64][68]
// ---------------------------------------------------------------------------
#define BQ 64
#define BKT 64
#define QS 68         // padded stride for transposed q/k tiles (mult of 4)
#define DP 96         // padded v columns (16*6)

__global__ __launch_bounds__(256) void attn_kernel()
{
    extern __shared__ float sm[];
    float* q_s = sm;                       // ND*QS = 5984
    float* k_s = q_s + ND * QS;            // 5984
    float* v_s = k_s + ND * QS;            // BKT*DP = 6144
    float* p_s = v_s + BKT * DP;           // BQ*QS = 4352

    const int qt = blockIdx.x;
    const int h  = blockIdx.y;
    const int b  = blockIdx.z;
    const int tid = threadIdx.x;
    const int tx = tid & 15;
    const int ty = tid >> 4;
    const int q0 = qt * BQ;

    const float* qbase = g_q + (size_t)b * NS * NE + (size_t)h * ND;
    const float* kbase = g_k + (size_t)b * NS * NE + (size_t)h * ND;
    const float* vbase = g_v + (size_t)b * NS * NE + (size_t)h * ND;

    // Load q tile transposed: q_s[d][r]
    for (int idx = tid; idx < BQ * ND; idx += 256) {
        int r = idx / ND;
        int d = idx - r * ND;
        float v = 0.f;
        if (q0 + r < NS) v = qbase[(size_t)(q0 + r) * NE + d];
        q_s[d * QS + r] = v;
    }

    float acc[4][6];
#pragma unroll
    for (int i = 0; i < 4; i++)
#pragma unroll
        for (int c = 0; c < 6; c++) acc[i][c] = 0.f;
    float mrow[4] = {-INFINITY, -INFINITY, -INFINITY, -INFINITY};
    float lrow[4] = {0.f, 0.f, 0.f, 0.f};

    const float scale = 0.10660035817780521f;  // 88^-0.5

    const int nkt = (NS + BKT - 1) / BKT;  // 17
    __syncthreads();

    for (int kt = 0; kt < nkt; kt++) {
        const int k0 = kt * BKT;

        // Load k transposed + v row-major
        for (int idx = tid; idx < BKT * ND; idx += 256) {
            int r = idx / ND;
            int d = idx - r * ND;
            float kv = 0.f, vv = 0.f;
            if (k0 + r < NS) {
                kv = kbase[(size_t)(k0 + r) * NE + d];
                vv = vbase[(size_t)(k0 + r) * NE + d];
            }
            k_s[d * QS + r] = kv;
            v_s[r * DP + d] = vv;
        }
        // Zero v padding cols (88..95)
        for (int idx = tid; idx < BKT * (DP - ND); idx += 256) {
            int r = idx >> 3;
            int d2 = idx & 7;
            v_s[r * DP + ND + d2] = 0.f;
        }
        __syncthreads();

        // Scores: s[i][j] = sum_d q[qy][d]*k[ky][d]
        float s[4][4];
#pragma unroll
        for (int i = 0; i < 4; i++)
#pragma unroll
            for (int j = 0; j < 4; j++) s[i][j] = 0.f;

#pragma unroll 8
        for (int d = 0; d < ND; d++) {
            float qa[4], kb[4];
            *(float4*)&qa[0] = *(const float4*)&q_s[d * QS + ty * 4];
            *(float4*)&kb[0] = *(const float4*)&k_s[d * QS + tx * 4];
#pragma unroll
            for (int i = 0; i < 4; i++)
#pragma unroll
                for (int j = 0; j < 4; j++)
                    s[i][j] += qa[i] * kb[j];
        }

        // Scale + key mask
#pragma unroll
        for (int i = 0; i < 4; i++)
#pragma unroll
            for (int j = 0; j < 4; j++) {
                s[i][j] *= scale;
                if (k0 + tx * 4 + j >= NS) s[i][j] = -INFINITY;
            }

        // Online softmax update
#pragma unroll
        for (int i = 0; i < 4; i++) {
            float mt = fmaxf(fmaxf(s[i][0], s[i][1]), fmaxf(s[i][2], s[i][3]));
#pragma unroll
            for (int off = 1; off < 16; off <<= 1)
                mt = fmaxf(mt, __shfl_xor_sync(0xffffffffu, mt, off));

            float mnew  = fmaxf(mrow[i], mt);
            float alpha = __expf(mrow[i] - mnew);
            mrow[i] = mnew;

            float rs = 0.f;
#pragma unroll
            for (int j = 0; j < 4; j++) {
                s[i][j] = __expf(s[i][j] - mnew);
                rs += s[i][j];
            }
#pragma unroll
            for (int off = 1; off < 16; off <<= 1)
                rs += __shfl_xor_sync(0xffffffffu, rs, off);

            lrow[i] = lrow[i] * alpha + rs;
#pragma unroll
            for (int c = 0; c < 6; c++) acc[i][c] *= alpha;
        }

        // Store P tile (float4, conflict-free: stride 68)
#pragma unroll
        for (int i = 0; i < 4; i++)
            *(float4*)&p_s[(ty * 4 + i) * QS + tx * 4] =
                make_float4(s[i][0], s[i][1], s[i][2], s[i][3]);
        __syncthreads();

        // acc += P @ V : each thread covers cols tx*6..tx*6+5
#pragma unroll 4
        for (int k = 0; k < BKT; k++) {
            float p0 = p_s[(ty * 4 + 0) * QS + k];
            float p1 = p_s[(ty * 4 + 1) * QS + k];
            float p2 = p_s[(ty * 4 + 2) * QS + k];
            float p3 = p_s[(ty * 4 + 3) * QS + k];
            float vv[6];
#pragma unroll
            for (int c = 0; c < 6; c++) vv[c] = v_s[k * DP + tx * 6 + c];
#pragma unroll
            for (int c = 0; c < 6; c++) {
                acc[0][c] += p0 * vv[c];
                acc[1][c] += p1 * vv[c];
                acc[2][c] += p2 * vv[c];
                acc[3][c] += p3 * vv[c];
            }
        }
        __syncthreads();
    }

    // Epilogue: ctx[b, q, h, :] = acc / l
    float* obase = g_ctx + (size_t)b * NS * NE + (size_t)h * ND;
#pragma unroll
    for (int i = 0; i < 4; i++) {
        int r = q0 + ty * 4 + i;
        if (r >= NS) continue;
        float inv = 1.f / lrow[i];
#pragma unroll
        for (int c = 0; c < 6; c++) {
            int col = tx * 6 + c;
            if (col < ND)
                obase[(size_t)r * NE + col] = acc[i][c] * inv;
        }
    }
}

// ---------------------------------------------------------------------------
// Launch
// ---------------------------------------------------------------------------
extern "C" void kernel_launch(void* const* d_in, const int* in_sizes, int n_in,
                              void* d_out, int out_size)
{
    const float* hidden = (const float*)d_in[0];
    const float* fcos   = (const float*)d_in[1];
    const float* fsin   = (const float*)d_in[2];
    const float* Wq     = (const float*)d_in[3];
    const float* bq     = (const float*)d_in[4];
    const float* Wk     = (const float*)d_in[5];
    const float* bk     = (const float*)d_in[6];
    const float* Wv     = (const float*)d_in[7];
    const float* bv     = (const float*)d_in[8];
    const float* Wo     = (const float*)d_in[9];
    const float* bo     = (const float*)d_in[10];
    float* out = (float*)d_out;

    float *qp, *kp, *vp, *ctxp;
    cudaGetSymbolAddress((void**)&qp,   g_q);
    cudaGetSymbolAddress((void**)&kp,   g_k);
    cudaGetSymbolAddress((void**)&vp,   g_v);
    cudaGetSymbolAddress((void**)&ctxp, g_ctx);

    dim3 gemm_grid((NE + 127) / 128, (NM + 127) / 128);  // (11, 65)

    gemm_bias_kernel<<<gemm_grid, 256>>>(hidden, Wq, bq, qp, NM, NE, NE);
    gemm_bias_kernel<<<gemm_grid, 256>>>(hidden, Wk, bk, kp, NM, NE, NE);
    gemm_bias_kernel<<<gemm_grid, 256>>>(hidden, Wv, bv, vp, NM, NE, NE);

    int rope_total = NM * NH * (ND / 2);
    rope_kernel<<<(rope_total + 255) / 256, 256>>>(fcos, fsin);

    size_t attn_smem = (size_t)(ND * QS * 2 + BKT * DP + BQ * QS) * sizeof(float); // 89856
    cudaFuncSetAttribute(attn_kernel,
                         cudaFuncAttributeMaxDynamicSharedMemorySize,
                         (int)attn_smem);
    dim3 attn_grid((NS + BQ - 1) / BQ, NH, NB);  // (17, 16, 8)
    attn_kernel<<<attn_grid, 256, attn_smem>>>();

    gemm_bias_kernel<<<gemm_grid, 256>>>(ctxp, Wo, bo, out, NM, NE, NE);
}

// round 4
// speedup vs baseline: 1.8349x; 1.8349x over previous
#include <cuda_runtime.h>
#include <cuda_bf16.h>
#include <math.h>
#include <stdint.h>

#define NB 8
#define NS 1025
#define NE 1408
#define NH 16
#define ND 88
#define NM (NB*NS)      // 8200

// Scratch (allocation-free rule: __device__ globals)
static __device__ float g_q[(size_t)NM * NE];
static __device__ float g_k[(size_t)NM * NE];
static __device__ float g_v[(size_t)NM * NE];
static __device__ float g_ctx[(size_t)NM * NE];

// ===========================================================================
// HMMA GEMM with bf16 split precision (no sm_103a-only PTX):
//   C[M,N] = A[M,K] * W[N,K]^T + bias[N]
// mma.sync.m16n8k16 bf16, fp32 accum. 3 terms: hi*hi + hi*lo + lo*hi.
// CTA tile 128x128, BK=32, 8 warps (2x4), warp tile 64x32.
// Smem rows stride 40 bf16 (80B) -> conflict-free ldmatrix.
// ===========================================================================
#define GK      NE            // 1408
#define BKC     32
#define NCHUNK  (GK / BKC)    // 44
#define SROW    40            // bf16 elems per smem row (80 bytes)
#define MAT_BYTES  (128 * SROW * 2)        // 10240
#define STAGE_BYTES (4 * MAT_BYTES)        // 40960 (Ahi, Alo, Bhi, Blo)
#define GEMM_SMEM  (2 * STAGE_BYTES)       // 81920

__device__ __forceinline__ uint32_t smem_to_u32(const void* p) {
    uint32_t a;
    asm("{ .reg .u64 t; cvta.to.shared.u64 t, %1; cvt.u32.u64 %0, t; }"
        : "=r"(a) : "l"(p));
    return a;
}

__device__ __forceinline__ void ldsm_x4(uint32_t* r, uint32_t addr) {
    asm volatile("ldmatrix.sync.aligned.m8n8.x4.shared.b16 {%0,%1,%2,%3}, [%4];"
                 : "=r"(r[0]), "=r"(r[1]), "=r"(r[2]), "=r"(r[3]) : "r"(addr));
}

__device__ __forceinline__ void mma_bf16(float* c, const uint32_t* a,
                                         const uint32_t* b) {
    asm volatile(
        "mma.sync.aligned.m16n8k16.row.col.f32.bf16.bf16.f32 "
        "{%0,%1,%2,%3}, {%4,%5,%6,%7}, {%8,%9}, {%0,%1,%2,%3};"
        : "+f"(c[0]), "+f"(c[1]), "+f"(c[2]), "+f"(c[3])
        : "r"(a[0]), "r"(a[1]), "r"(a[2]), "r"(a[3]), "r"(b[0]), "r"(b[1]));
}

// split 8 fp32 -> 8 bf16 hi + 8 bf16 lo (packed as uint4 each)
__device__ __forceinline__ void split8(const float* x, uint4* hi, uint4* lo) {
    union { __nv_bfloat162 h2[4]; uint4 u; } ph, pl;
#pragma unroll
    for (int j = 0; j < 4; j++) {
        float2 f2 = make_float2(x[2 * j], x[2 * j + 1]);
        __nv_bfloat162 h = __float22bfloat162_rn(f2);
        float2 hf = __bfloat1622float2(h);
        ph.h2[j] = h;
        pl.h2[j] = __float22bfloat162_rn(make_float2(f2.x - hf.x, f2.y - hf.y));
    }
    *hi = ph.u;
    *lo = pl.u;
}

__global__ __launch_bounds__(256) void gemm_hmma_kernel(
    const float* __restrict__ A, const float* __restrict__ W,
    const float* __restrict__ bias, float* __restrict__ C, int M)
{
    extern __shared__ char sm[];
    const uint32_t smemu = smem_to_u32(sm);
    const int tid  = threadIdx.x;
    const int wid  = tid >> 5;
    const int lane = tid & 31;
    const int bm = blockIdx.y * 128;
    const int bn = blockIdx.x * 128;

    const int wm = (wid >> 2) * 64;    // warp m offset (0 or 64)
    const int wn = (wid & 3) * 32;     // warp n offset (0,32,64,96)

    // Per-thread load assignment: 2 segments of 8 consecutive k each, per matrix
    int rowL[2], kcL[2];
#pragma unroll
    for (int i = 0; i < 2; i++) {
        int seg = tid + i * 256;
        rowL[i] = seg >> 2;            // 0..127
        kcL[i]  = (seg & 3) << 3;      // 0,8,16,24
    }

    // ldmatrix per-lane byte offsets (within a matrix)
    const uint32_t aoff =
        (uint32_t)((wm + ((lane >> 3) & 1) * 8 + (lane & 7)) * (SROW * 2)
                   + (lane >> 4) * 16);
    const uint32_t boff =
        (uint32_t)((wn + ((lane >> 4) << 3) + (lane & 7)) * (SROW * 2)
                   + ((lane >> 3) & 1) * 16);

    float acc[4][4][4];
#pragma unroll
    for (int mi = 0; mi < 4; mi++)
#pragma unroll
        for (int ni = 0; ni < 4; ni++)
#pragma unroll
            for (int j = 0; j < 4; j++) acc[mi][ni][j] = 0.f;

    float ar[16], br[16];

    // ---- load chunk 0 into regs ----
#pragma unroll
    for (int i = 0; i < 2; i++) {
        int gr = bm + rowL[i];
        if (gr < M) {
            *(float4*)&ar[i * 8]     = *(const float4*)(A + (size_t)gr * GK + kcL[i]);
            *(float4*)&ar[i * 8 + 4] = *(const float4*)(A + (size_t)gr * GK + kcL[i] + 4);
        } else {
#pragma unroll
            for (int j = 0; j < 8; j++) ar[i * 8 + j] = 0.f;
        }
        int gn = bn + rowL[i];
        *(float4*)&br[i * 8]     = *(const float4*)(W + (size_t)gn * GK + kcL[i]);
        *(float4*)&br[i * 8 + 4] = *(const float4*)(W + (size_t)gn * GK + kcL[i] + 4);
    }
    // ---- STS chunk 0 to stage 0 ----
#pragma unroll
    for (int i = 0; i < 2; i++) {
        uint32_t off = (uint32_t)(rowL[i] * (SROW * 2) + kcL[i] * 2);
        uint4 hi, lo;
        split8(&ar[i * 8], &hi, &lo);
        *(uint4*)(sm + off)             = hi;
        *(uint4*)(sm + MAT_BYTES + off) = lo;
        split8(&br[i * 8], &hi, &lo);
        *(uint4*)(sm + 2 * MAT_BYTES + off) = hi;
        *(uint4*)(sm + 3 * MAT_BYTES + off) = lo;
    }
    __syncthreads();

#pragma unroll 1
    for (int c = 0; c < NCHUNK; c++) {
        // prefetch next chunk into regs
        if (c + 1 < NCHUNK) {
            const int k0 = (c + 1) * BKC;
#pragma unroll
            for (int i = 0; i < 2; i++) {
                int gr = bm + rowL[i];
                if (gr < M) {
                    *(float4*)&ar[i * 8]     = *(const float4*)(A + (size_t)gr * GK + k0 + kcL[i]);
                    *(float4*)&ar[i * 8 + 4] = *(const float4*)(A + (size_t)gr * GK + k0 + kcL[i] + 4);
                } else {
#pragma unroll
                    for (int j = 0; j < 8; j++) ar[i * 8 + j] = 0.f;
                }
                int gn = bn + rowL[i];
                *(float4*)&br[i * 8]     = *(const float4*)(W + (size_t)gn * GK + k0 + kcL[i]);
                *(float4*)&br[i * 8 + 4] = *(const float4*)(W + (size_t)gn * GK + k0 + kcL[i] + 4);
            }
        }

        // compute current stage
        {
            const uint32_t base = smemu + (uint32_t)((c & 1) * STAGE_BYTES);
            const uint32_t aHi = base;
            const uint32_t aLo = base + MAT_BYTES;
            const uint32_t bHi = base + 2 * MAT_BYTES;
            const uint32_t bLo = base + 3 * MAT_BYTES;

#pragma unroll
            for (int ks = 0; ks < 2; ks++) {
                const uint32_t ksb = ks * 32;   // 16 bf16 = 32 bytes
                uint32_t ah[16], al[16], bh[8], bl[8];
#pragma unroll
                for (int mi = 0; mi < 4; mi++) {
                    ldsm_x4(&ah[mi * 4], aHi + aoff + mi * 16 * (SROW * 2) + ksb);
                    ldsm_x4(&al[mi * 4], aLo + aoff + mi * 16 * (SROW * 2) + ksb);
                }
                ldsm_x4(&bh[0], bHi + boff + ksb);
                ldsm_x4(&bh[4], bHi + boff + 16 * (SROW * 2) + ksb);
                ldsm_x4(&bl[0], bLo + boff + ksb);
                ldsm_x4(&bl[4], bLo + boff + 16 * (SROW * 2) + ksb);

#pragma unroll
                for (int mi = 0; mi < 4; mi++)
#pragma unroll
                    for (int ni = 0; ni < 4; ni++) {
                        mma_bf16(acc[mi][ni], &ah[mi * 4], &bh[ni * 2]);
                        mma_bf16(acc[mi][ni], &ah[mi * 4], &bl[ni * 2]);
                        mma_bf16(acc[mi][ni], &al[mi * 4], &bh[ni * 2]);
                    }
            }
        }

        // STS next chunk into other stage
        if (c + 1 < NCHUNK) {
            char* stage = sm + ((c + 1) & 1) * STAGE_BYTES;
#pragma unroll
            for (int i = 0; i < 2; i++) {
                uint32_t off = (uint32_t)(rowL[i] * (SROW * 2) + kcL[i] * 2);
                uint4 hi, lo;
                split8(&ar[i * 8], &hi, &lo);
                *(uint4*)(stage + off)             = hi;
                *(uint4*)(stage + MAT_BYTES + off) = lo;
                split8(&br[i * 8], &hi, &lo);
                *(uint4*)(stage + 2 * MAT_BYTES + off) = hi;
                *(uint4*)(stage + 3 * MAT_BYTES + off) = lo;
            }
        }
        __syncthreads();
    }

    // ---- epilogue: direct STG with bias ----
    const int r0 = bm + wm + (lane >> 2);
    const int c0 = bn + wn + (lane & 3) * 2;
#pragma unroll
    for (int mi = 0; mi < 4; mi++) {
#pragma unroll
        for (int ni = 0; ni < 4; ni++) {
            int gc = c0 + ni * 8;
            float bx = bias[gc], by = bias[gc + 1];
            int gr = r0 + mi * 16;
            if (gr < M) {
                float2 o = make_float2(acc[mi][ni][0] + bx, acc[mi][ni][1] + by);
                *(float2*)(C + (size_t)gr * NE + gc) = o;
            }
            if (gr + 8 < M) {
                float2 o = make_float2(acc[mi][ni][2] + bx, acc[mi][ni][3] + by);
                *(float2*)(C + (size_t)(gr + 8) * NE + gc) = o;
            }
        }
    }
}

// ---------------------------------------------------------------------------
// RoPE applied in-place to g_q and g_k.
// ---------------------------------------------------------------------------
__global__ void rope_kernel(const float* __restrict__ fcos,
                            const float* __restrict__ fsin)
{
    const int HALF = ND / 2;  // 44
    int idx = blockIdx.x * blockDim.x + threadIdx.x;
    int total = NM * NH * HALF;
    if (idx >= total) return;

    int p = idx % HALF;
    int t = idx / HALF;
    int h = t % NH;
    int m = t / NH;
    int s = m % NS;

    float c  = fcos[s * HALF + p];
    float sn = fsin[s * HALF + p];

    size_t base = (size_t)m * NE + h * ND + 2 * p;

    float xr = g_q[base], xi = g_q[base + 1];
    g_q[base]     = xr * c  - xi * sn;
    g_q[base + 1] = xr * sn + xi * c;

    xr = g_k[base]; xi = g_k[base + 1];
    g_k[base]     = xr * c  - xi * sn;
    g_k[base + 1] = xr * sn + xi * c;
}

// ---------------------------------------------------------------------------
// Flash-style attention, fp32 (unchanged from R2 passing kernel).
// ---------------------------------------------------------------------------
#define BQ 64
#define BKT 64
#define QS 68
#define DP 96

__global__ __launch_bounds__(256) void attn_kernel()
{
    extern __shared__ float smf[];
    float* q_s = smf;
    float* k_s = q_s + ND * QS;
    float* v_s = k_s + ND * QS;
    float* p_s = v_s + BKT * DP;

    const int qt = blockIdx.x;
    const int h  = blockIdx.y;
    const int b  = blockIdx.z;
    const int tid = threadIdx.x;
    const int tx = tid & 15;
    const int ty = tid >> 4;
    const int q0 = qt * BQ;

    const float* qbase = g_q + (size_t)b * NS * NE + (size_t)h * ND;
    const float* kbase = g_k + (size_t)b * NS * NE + (size_t)h * ND;
    const float* vbase = g_v + (size_t)b * NS * NE + (size_t)h * ND;

    for (int idx = tid; idx < BQ * ND; idx += 256) {
        int r = idx / ND;
        int d = idx - r * ND;
        float v = 0.f;
        if (q0 + r < NS) v = qbase[(size_t)(q0 + r) * NE + d];
        q_s[d * QS + r] = v;
    }

    float acc[4][6];
#pragma unroll
    for (int i = 0; i < 4; i++)
#pragma unroll
        for (int c = 0; c < 6; c++) acc[i][c] = 0.f;
    float mrow[4] = {-INFINITY, -INFINITY, -INFINITY, -INFINITY};
    float lrow[4] = {0.f, 0.f, 0.f, 0.f};

    const float scale = 0.10660035817780521f;

    const int nkt = (NS + BKT - 1) / BKT;
    __syncthreads();

    for (int kt = 0; kt < nkt; kt++) {
        const int k0 = kt * BKT;

        for (int idx = tid; idx < BKT * ND; idx += 256) {
            int r = idx / ND;
            int d = idx - r * ND;
            float kv = 0.f, vv = 0.f;
            if (k0 + r < NS) {
                kv = kbase[(size_t)(k0 + r) * NE + d];
                vv = vbase[(size_t)(k0 + r) * NE + d];
            }
            k_s[d * QS + r] = kv;
            v_s[r * DP + d] = vv;
        }
        for (int idx = tid; idx < BKT * (DP - ND); idx += 256) {
            int r = idx >> 3;
            int d2 = idx & 7;
            v_s[r * DP + ND + d2] = 0.f;
        }
        __syncthreads();

        float s[4][4];
#pragma unroll
        for (int i = 0; i < 4; i++)
#pragma unroll
            for (int j = 0; j < 4; j++) s[i][j] = 0.f;

#pragma unroll 8
        for (int d = 0; d < ND; d++) {
            float qa[4], kb[4];
            *(float4*)&qa[0] = *(const float4*)&q_s[d * QS + ty * 4];
            *(float4*)&kb[0] = *(const float4*)&k_s[d * QS + tx * 4];
#pragma unroll
            for (int i = 0; i < 4; i++)
#pragma unroll
                for (int j = 0; j < 4; j++)
                    s[i][j] += qa[i] * kb[j];
        }

#pragma unroll
        for (int i = 0; i < 4; i++)
#pragma unroll
            for (int j = 0; j < 4; j++) {
                s[i][j] *= scale;
                if (k0 + tx * 4 + j >= NS) s[i][j] = -INFINITY;
            }

#pragma unroll
        for (int i = 0; i < 4; i++) {
            float mt = fmaxf(fmaxf(s[i][0], s[i][1]), fmaxf(s[i][2], s[i][3]));
#pragma unroll
            for (int off = 1; off < 16; off <<= 1)
                mt = fmaxf(mt, __shfl_xor_sync(0xffffffffu, mt, off));

            float mnew  = fmaxf(mrow[i], mt);
            float alpha = __expf(mrow[i] - mnew);
            mrow[i] = mnew;

            float rs = 0.f;
#pragma unroll
            for (int j = 0; j < 4; j++) {
                s[i][j] = __expf(s[i][j] - mnew);
                rs += s[i][j];
            }
#pragma unroll
            for (int off = 1; off < 16; off <<= 1)
                rs += __shfl_xor_sync(0xffffffffu, rs, off);

            lrow[i] = lrow[i] * alpha + rs;
#pragma unroll
            for (int c = 0; c < 6; c++) acc[i][c] *= alpha;
        }

#pragma unroll
        for (int i = 0; i < 4; i++)
            *(float4*)&p_s[(ty * 4 + i) * QS + tx * 4] =
                make_float4(s[i][0], s[i][1], s[i][2], s[i][3]);
        __syncthreads();

#pragma unroll 4
        for (int k = 0; k < BKT; k++) {
            float p0 = p_s[(ty * 4 + 0) * QS + k];
            float p1 = p_s[(ty * 4 + 1) * QS + k];
            float p2 = p_s[(ty * 4 + 2) * QS + k];
            float p3 = p_s[(ty * 4 + 3) * QS + k];
            float vv[6];
#pragma unroll
            for (int c = 0; c < 6; c++) vv[c] = v_s[k * DP + tx * 6 + c];
#pragma unroll
            for (int c = 0; c < 6; c++) {
                acc[0][c] += p0 * vv[c];
                acc[1][c] += p1 * vv[c];
                acc[2][c] += p2 * vv[c];
                acc[3][c] += p3 * vv[c];
            }
        }
        __syncthreads();
    }

    float* obase = g_ctx + (size_t)b * NS * NE + (size_t)h * ND;
#pragma unroll
    for (int i = 0; i < 4; i++) {
        int r = q0 + ty * 4 + i;
        if (r >= NS) continue;
        float inv = 1.f / lrow[i];
#pragma unroll
        for (int c = 0; c < 6; c++) {
            int col = tx * 6 + c;
            if (col < ND)
                obase[(size_t)r * NE + col] = acc[i][c] * inv;
        }
    }
}

// ---------------------------------------------------------------------------
// Launch
// ---------------------------------------------------------------------------
extern "C" void kernel_launch(void* const* d_in, const int* in_sizes, int n_in,
                              void* d_out, int out_size)
{
    const float* hidden = (const float*)d_in[0];
    const float* fcos   = (const float*)d_in[1];
    const float* fsin   = (const float*)d_in[2];
    const float* Wq     = (const float*)d_in[3];
    const float* bq     = (const float*)d_in[4];
    const float* Wk     = (const float*)d_in[5];
    const float* bk     = (const float*)d_in[6];
    const float* Wv     = (const float*)d_in[7];
    const float* bv     = (const float*)d_in[8];
    const float* Wo     = (const float*)d_in[9];
    const float* bo     = (const float*)d_in[10];
    float* out = (float*)d_out;

    float *qp, *kp, *vp, *ctxp;
    cudaGetSymbolAddress((void**)&qp,   g_q);
    cudaGetSymbolAddress((void**)&kp,   g_k);
    cudaGetSymbolAddress((void**)&vp,   g_v);
    cudaGetSymbolAddress((void**)&ctxp, g_ctx);

    static int smem_set = 0;
    if (!smem_set) {
        cudaFuncSetAttribute(gemm_hmma_kernel,
                             cudaFuncAttributeMaxDynamicSharedMemorySize, GEMM_SMEM);
        size_t attn_smem = (size_t)(ND * QS * 2 + BKT * DP + BQ * QS) * sizeof(float);
        cudaFuncSetAttribute(attn_kernel,
                             cudaFuncAttributeMaxDynamicSharedMemorySize, (int)attn_smem);
        smem_set = 1;
    }

    dim3 gemm_grid(NE / 128, (NM + 127) / 128);  // (11, 65)

    gemm_hmma_kernel<<<gemm_grid, 256, GEMM_SMEM>>>(hidden, Wq, bq, qp, NM);
    gemm_hmma_kernel<<<gemm_grid, 256, GEMM_SMEM>>>(hidden, Wk, bk, kp, NM);
    gemm_hmma_kernel<<<gemm_grid, 256, GEMM_SMEM>>>(hidden, Wv, bv, vp, NM);

    int rope_total = NM * NH * (ND / 2);
    rope_kernel<<<(rope_total + 255) / 256, 256>>>(fcos, fsin);

    size_t attn_smem = (size_t)(ND * QS * 2 + BKT * DP + BQ * QS) * sizeof(float);
    dim3 attn_grid((NS + BQ - 1) / BQ, NH, NB);  // (17, 16, 8)
    attn_kernel<<<attn_grid, 256, attn_smem>>>();

    gemm_hmma_kernel<<<gemm_grid, 256, GEMM_SMEM>>>(ctxp, Wo, bo, out, NM);
}

// round 6
// speedup vs baseline: 2.9344x; 1.5992x over previous
#include <cuda_runtime.h>
#include <cuda_bf16.h>
#include <math.h>
#include <stdint.h>

#define NB 8
#define NS 1025
#define NE 1408
#define NH 16
#define ND 88
#define NM (NB*NS)      // 8200
#define DPAD 96
#define QKROW (NH*DPAD) // 1536
#define SVT 1088        // padded token dim for V^T (17*64)

// Scratch (__device__ globals are zero-initialized at module load; padding
// regions are never written, so they stay zero — used as MMA zero-padding).
static __device__ float g_ctx[(size_t)NM * NE];
static __device__ __nv_bfloat16 g_qh[(size_t)NM * QKROW];
static __device__ __nv_bfloat16 g_ql[(size_t)NM * QKROW];
static __device__ __nv_bfloat16 g_kh[(size_t)NM * QKROW];
static __device__ __nv_bfloat16 g_kl[(size_t)NM * QKROW];
static __device__ __nv_bfloat16 g_vth[(size_t)NB * NH * DPAD * SVT];
static __device__ __nv_bfloat16 g_vtl[(size_t)NB * NH * DPAD * SVT];

// ===========================================================================
// Common helpers
// ===========================================================================
__device__ __forceinline__ uint32_t smem_to_u32(const void* p) {
    uint32_t a;
    asm("{ .reg .u64 t; cvta.to.shared.u64 t, %1; cvt.u32.u64 %0, t; }"
        : "=r"(a) : "l"(p));
    return a;
}
__device__ __forceinline__ void ldsm_x4(uint32_t* r, uint32_t addr) {
    asm volatile("ldmatrix.sync.aligned.m8n8.x4.shared.b16 {%0,%1,%2,%3}, [%4];"
                 : "=r"(r[0]), "=r"(r[1]), "=r"(r[2]), "=r"(r[3]) : "r"(addr));
}
__device__ __forceinline__ void mma_bf16(float* c, const uint32_t* a,
                                         const uint32_t* b) {
    asm volatile(
        "mma.sync.aligned.m16n8k16.row.col.f32.bf16.bf16.f32 "
        "{%0,%1,%2,%3}, {%4,%5,%6,%7}, {%8,%9}, {%0,%1,%2,%3};"
        : "+f"(c[0]), "+f"(c[1]), "+f"(c[2]), "+f"(c[3])
        : "r"(a[0]), "r"(a[1]), "r"(a[2]), "r"(a[3]), "r"(b[0]), "r"(b[1]));
}
__device__ __forceinline__ void cp16(uint32_t dst, const void* src) {
    asm volatile("cp.async.cg.shared.global [%0], [%1], 16;"
                 :: "r"(dst), "l"(__cvta_generic_to_global(src)));
}
#define CP_COMMIT() asm volatile("cp.async.commit_group;" ::: "memory")
#define CP_WAIT0()  asm volatile("cp.async.wait_group 0;" ::: "memory")

__device__ __forceinline__ void split8(const float* x, uint4* hi, uint4* lo) {
    union { __nv_bfloat162 h2[4]; uint4 u; } ph, pl;
#pragma unroll
    for (int j = 0; j < 4; j++) {
        float2 f2 = make_float2(x[2 * j], x[2 * j + 1]);
        __nv_bfloat162 h = __float22bfloat162_rn(f2);
        float2 hf = __bfloat1622float2(h);
        ph.h2[j] = h;
        pl.h2[j] = __float22bfloat162_rn(make_float2(f2.x - hf.x, f2.y - hf.y));
    }
    *hi = ph.u;
    *lo = pl.u;
}
__device__ __forceinline__ void bsplit(float x, __nv_bfloat16& h, __nv_bfloat16& l) {
    h = __float2bfloat16(x);
    l = __float2bfloat16(x - __bfloat162float(h));
}

// ===========================================================================
// HMMA GEMM, split bf16 (3 terms).  C[M,N] = A[M,K]*W[N,K]^T + bias
// MODE 0: fp32 out.  MODE 1: RoPE + bf16 hi/lo to padded [m][1536].
// MODE 2: bf16 hi/lo transposed to [b,h,96,1088].
// ===========================================================================
#define GK      NE
#define BKC     32
#define NCHUNK  (GK / BKC)    // 44
#define SROW    40
#define MAT_BYTES  (128 * SROW * 2)
#define STAGE_BYTES (4 * MAT_BYTES)
#define GEMM_SMEM  (2 * STAGE_BYTES)

template<int MODE>
__global__ __launch_bounds__(256) void gemm_hmma_kernel(
    const float* __restrict__ A, const float* __restrict__ W,
    const float* __restrict__ bias, float* __restrict__ C,
    __nv_bfloat16* __restrict__ Oh, __nv_bfloat16* __restrict__ Ol,
    const float* __restrict__ rcos, const float* __restrict__ rsin, int M)
{
    extern __shared__ char sm[];
    const uint32_t smemu = smem_to_u32(sm);
    const int tid  = threadIdx.x;
    const int wid  = tid >> 5;
    const int lane = tid & 31;
    const int bm = blockIdx.y * 128;
    const int bn = blockIdx.x * 128;

    const int wm = (wid >> 2) * 64;
    const int wn = (wid & 3) * 32;

    int rowL[2], kcL[2];
#pragma unroll
    for (int i = 0; i < 2; i++) {
        int seg = tid + i * 256;
        rowL[i] = seg >> 2;
        kcL[i]  = (seg & 3) << 3;
    }

    const uint32_t aoff =
        (uint32_t)((wm + ((lane >> 3) & 1) * 8 + (lane & 7)) * (SROW * 2)
                   + (lane >> 4) * 16);
    const uint32_t boff =
        (uint32_t)((wn + ((lane >> 4) << 3) + (lane & 7)) * (SROW * 2)
                   + ((lane >> 3) & 1) * 16);

    float acc[4][4][4];
#pragma unroll
    for (int mi = 0; mi < 4; mi++)
#pragma unroll
        for (int ni = 0; ni < 4; ni++)
#pragma unroll
            for (int j = 0; j < 4; j++) acc[mi][ni][j] = 0.f;

    float ar[16], br[16];

#pragma unroll
    for (int i = 0; i < 2; i++) {
        int gr = bm + rowL[i];
        if (gr < M) {
            *(float4*)&ar[i * 8]     = *(const float4*)(A + (size_t)gr * GK + kcL[i]);
            *(float4*)&ar[i * 8 + 4] = *(const float4*)(A + (size_t)gr * GK + kcL[i] + 4);
        } else {
#pragma unroll
            for (int j = 0; j < 8; j++) ar[i * 8 + j] = 0.f;
        }
        int gn = bn + rowL[i];
        *(float4*)&br[i * 8]     = *(const float4*)(W + (size_t)gn * GK + kcL[i]);
        *(float4*)&br[i * 8 + 4] = *(const float4*)(W + (size_t)gn * GK + kcL[i] + 4);
    }
#pragma unroll
    for (int i = 0; i < 2; i++) {
        uint32_t off = (uint32_t)(rowL[i] * (SROW * 2) + kcL[i] * 2);
        uint4 hi, lo;
        split8(&ar[i * 8], &hi, &lo);
        *(uint4*)(sm + off)             = hi;
        *(uint4*)(sm + MAT_BYTES + off) = lo;
        split8(&br[i * 8], &hi, &lo);
        *(uint4*)(sm + 2 * MAT_BYTES + off) = hi;
        *(uint4*)(sm + 3 * MAT_BYTES + off) = lo;
    }
    __syncthreads();

#pragma unroll 1
    for (int c = 0; c < NCHUNK; c++) {
        if (c + 1 < NCHUNK) {
            const int k0 = (c + 1) * BKC;
#pragma unroll
            for (int i = 0; i < 2; i++) {
                int gr = bm + rowL[i];
                if (gr < M) {
                    *(float4*)&ar[i * 8]     = *(const float4*)(A + (size_t)gr * GK + k0 + kcL[i]);
                    *(float4*)&ar[i * 8 + 4] = *(const float4*)(A + (size_t)gr * GK + k0 + kcL[i] + 4);
                } else {
#pragma unroll
                    for (int j = 0; j < 8; j++) ar[i * 8 + j] = 0.f;
                }
                int gn = bn + rowL[i];
                *(float4*)&br[i * 8]     = *(const float4*)(W + (size_t)gn * GK + k0 + kcL[i]);
                *(float4*)&br[i * 8 + 4] = *(const float4*)(W + (size_t)gn * GK + k0 + kcL[i] + 4);
            }
        }
        {
            const uint32_t base = smemu + (uint32_t)((c & 1) * STAGE_BYTES);
            const uint32_t aHi = base;
            const uint32_t aLo = base + MAT_BYTES;
            const uint32_t bHi = base + 2 * MAT_BYTES;
            const uint32_t bLo = base + 3 * MAT_BYTES;
#pragma unroll
            for (int ks = 0; ks < 2; ks++) {
                const uint32_t ksb = ks * 32;
                uint32_t ah[16], al[16], bh[8], bl[8];
#pragma unroll
                for (int mi = 0; mi < 4; mi++) {
                    ldsm_x4(&ah[mi * 4], aHi + aoff + mi * 16 * (SROW * 2) + ksb);
                    ldsm_x4(&al[mi * 4], aLo + aoff + mi * 16 * (SROW * 2) + ksb);
                }
                ldsm_x4(&bh[0], bHi + boff + ksb);
                ldsm_x4(&bh[4], bHi + boff + 16 * (SROW * 2) + ksb);
                ldsm_x4(&bl[0], bLo + boff + ksb);
                ldsm_x4(&bl[4], bLo + boff + 16 * (SROW * 2) + ksb);
#pragma unroll
                for (int mi = 0; mi < 4; mi++)
#pragma unroll
                    for (int ni = 0; ni < 4; ni++) {
                        mma_bf16(acc[mi][ni], &ah[mi * 4], &bh[ni * 2]);
                        mma_bf16(acc[mi][ni], &ah[mi * 4], &bl[ni * 2]);
                        mma_bf16(acc[mi][ni], &al[mi * 4], &bh[ni * 2]);
                    }
            }
        }
        if (c + 1 < NCHUNK) {
            char* stage = sm + ((c + 1) & 1) * STAGE_BYTES;
#pragma unroll
            for (int i = 0; i < 2; i++) {
                uint32_t off = (uint32_t)(rowL[i] * (SROW * 2) + kcL[i] * 2);
                uint4 hi, lo;
                split8(&ar[i * 8], &hi, &lo);
                *(uint4*)(stage + off)             = hi;
                *(uint4*)(stage + MAT_BYTES + off) = lo;
                split8(&br[i * 8], &hi, &lo);
                *(uint4*)(stage + 2 * MAT_BYTES + off) = hi;
                *(uint4*)(stage + 3 * MAT_BYTES + off) = lo;
            }
        }
        __syncthreads();
    }

    // ---- epilogue ----
    const int r0 = bm + wm + (lane >> 2);
    const int c0 = bn + wn + (lane & 3) * 2;
#pragma unroll
    for (int mi = 0; mi < 4; mi++) {
#pragma unroll
        for (int ni = 0; ni < 4; ni++) {
            const int gc = c0 + ni * 8;
            const float bx = bias[gc], by = bias[gc + 1];
            const int hh = gc / ND;
            const int dd = gc - hh * ND;
#pragma unroll
            for (int half = 0; half < 2; half++) {
                const int gr = r0 + mi * 16 + half * 8;
                if (gr >= M) continue;
                float xr = acc[mi][ni][2 * half + 0] + bx;
                float xi = acc[mi][ni][2 * half + 1] + by;
                if (MODE == 0) {
                    *(float2*)(C + (size_t)gr * NE + gc) = make_float2(xr, xi);
                } else if (MODE == 1) {
                    const int st = gr % NS;
                    const float cc = rcos[st * (ND / 2) + (dd >> 1)];
                    const float ss = rsin[st * (ND / 2) + (dd >> 1)];
                    float orr = xr * cc - xi * ss;
                    float oii = xr * ss + xi * cc;
                    __nv_bfloat16 h0, l0, h1, l1;
                    bsplit(orr, h0, l0);
                    bsplit(oii, h1, l1);
                    size_t off = (size_t)gr * QKROW + hh * DPAD + dd;
                    *(__nv_bfloat162*)(Oh + off) = __halves2bfloat162(h0, h1);
                    *(__nv_bfloat162*)(Ol + off) = __halves2bfloat162(l0, l1);
                } else {
                    const int bb = gr / NS;
                    const int st = gr - bb * NS;
                    size_t base = ((size_t)((bb * NH + hh) * DPAD) + dd) * SVT + st;
                    __nv_bfloat16 h0, l0, h1, l1;
                    bsplit(xr, h0, l0);
                    bsplit(xi, h1, l1);
                    Oh[base]       = h0;
                    Ol[base]       = l0;
                    Oh[base + SVT] = h1;
                    Ol[base + SVT] = l1;
                }
            }
        }
    }
}

// ===========================================================================
// HMMA flash attention, split bf16 (3 terms both GEMMs).
// BQ=64, BK=64, 4 warps. Q fragments register-resident.
// ===========================================================================
#define KSTB 208    // K/Q smem row stride bytes (13*16, conflict-free)
#define VSTB 144    // V^T / P smem row stride bytes (9*16)
#define OFF_KH 0
#define OFF_KL 13312
#define OFF_VH 26624
#define OFF_VL 40448
#define OFF_PH 54272
#define OFF_PL 63488
#define ATT_SMEM 72704

__global__ __launch_bounds__(128) void attn_hmma_kernel()
{
    extern __shared__ char sm[];
    const uint32_t smemu = smem_to_u32(sm);
    const int tid  = threadIdx.x;
    const int wid  = tid >> 5;
    const int lane = tid & 31;
    const int wm   = wid * 16;

    const int qt = blockIdx.x, h = blockIdx.y, b = blockIdx.z;
    const int q0 = qt * 64;

    const char* qh_base = (const char*)(g_qh + (size_t)b * NS * QKROW + h * DPAD);
    const char* ql_base = (const char*)(g_ql + (size_t)b * NS * QKROW + h * DPAD);
    const char* kh_base = (const char*)(g_kh + (size_t)b * NS * QKROW + h * DPAD);
    const char* kl_base = (const char*)(g_kl + (size_t)b * NS * QKROW + h * DPAD);
    const char* vh_base = (const char*)(g_vth + (size_t)(b * NH + h) * DPAD * SVT);
    const char* vl_base = (const char*)(g_vtl + (size_t)(b * NH + h) * DPAD * SVT);

    // ---- stage Q into K buffers, build register fragments ----
    for (int i = tid; i < 768; i += 128) {
        int row = i / 12, ch = i % 12;
        int tok = q0 + row; if (tok > NS - 1) tok = NS - 1;
        size_t gb = (size_t)tok * (QKROW * 2) + ch * 16;
        cp16(smemu + OFF_KH + row * KSTB + ch * 16, qh_base + gb);
        cp16(smemu + OFF_KL + row * KSTB + ch * 16, ql_base + gb);
    }
    CP_COMMIT(); CP_WAIT0();
    __syncthreads();

    const uint32_t aoffQ = (uint32_t)((wm + ((lane >> 3) & 1) * 8 + (lane & 7)) * KSTB
                                      + (lane >> 4) * 16);
    uint32_t qhf[6][4], qlf[6][4];
#pragma unroll
    for (int ks = 0; ks < 6; ks++) {
        ldsm_x4(qhf[ks], smemu + OFF_KH + aoffQ + ks * 32);
        ldsm_x4(qlf[ks], smemu + OFF_KL + aoffQ + ks * 32);
    }
    __syncthreads();

    float acc_o[11][4];
#pragma unroll
    for (int nt = 0; nt < 11; nt++)
#pragma unroll
        for (int j = 0; j < 4; j++) acc_o[nt][j] = 0.f;
    float mrun[2] = {-INFINITY, -INFINITY};
    float lrun[2] = {0.f, 0.f};

    const float scale = 0.10660035817780521f;
    const uint32_t kboff = (uint32_t)((((lane >> 4) << 3) + (lane & 7)) * KSTB
                                      + ((lane >> 3) & 1) * 16);
    const uint32_t vboff = (uint32_t)((((lane >> 4) << 3) + (lane & 7)) * VSTB
                                      + ((lane >> 3) & 1) * 16);
    const uint32_t apoff = (uint32_t)((wm + ((lane >> 3) & 1) * 8 + (lane & 7)) * VSTB
                                      + (lane >> 4) * 16);
    const int colb = (lane & 3) * 2;
    const int prow_lo = wm + (lane >> 2);

#pragma unroll 1
    for (int kt = 0; kt < 17; kt++) {
        const int k0 = kt * 64;

        // load K (64 rows x 12 ch) and V^T (96 rows x 8 ch), hi+lo
        for (int i = tid; i < 768; i += 128) {
            int rk = i / 12, ck = i % 12;
            int tok = k0 + rk; if (tok > NS - 1) tok = NS - 1;
            size_t gk = (size_t)tok * (QKROW * 2) + ck * 16;
            cp16(smemu + OFF_KH + rk * KSTB + ck * 16, kh_base + gk);
            cp16(smemu + OFF_KL + rk * KSTB + ck * 16, kl_base + gk);
            int rv = i / 8, cv = i % 8;
            size_t gv = (size_t)rv * (SVT * 2) + k0 * 2 + cv * 16;
            cp16(smemu + OFF_VH + rv * VSTB + cv * 16, vh_base + gv);
            cp16(smemu + OFF_VL + rv * VSTB + cv * 16, vl_base + gv);
        }
        CP_COMMIT(); CP_WAIT0();
        __syncthreads();

        // ---- S = Q K^T (3-term split) ----
        float sacc[8][4];
#pragma unroll
        for (int nt = 0; nt < 8; nt++)
#pragma unroll
            for (int j = 0; j < 4; j++) sacc[nt][j] = 0.f;

#pragma unroll
        for (int ks = 0; ks < 6; ks++) {
            uint32_t kbh[16], kbl[16];
#pragma unroll
            for (int j = 0; j < 4; j++) {
                ldsm_x4(&kbh[j * 4], smemu + OFF_KH + kboff + j * 16 * KSTB + ks * 32);
                ldsm_x4(&kbl[j * 4], smemu + OFF_KL + kboff + j * 16 * KSTB + ks * 32);
            }
#pragma unroll
            for (int nt = 0; nt < 8; nt++) {
                mma_bf16(sacc[nt], qhf[ks], &kbh[nt * 2]);
                mma_bf16(sacc[nt], qhf[ks], &kbl[nt * 2]);
                mma_bf16(sacc[nt], qlf[ks], &kbh[nt * 2]);
            }
        }

        // scale + mask
#pragma unroll
        for (int nt = 0; nt < 8; nt++)
#pragma unroll
            for (int j = 0; j < 4; j++) sacc[nt][j] *= scale;
        if (k0 + 64 > NS) {
#pragma unroll
            for (int nt = 0; nt < 8; nt++)
#pragma unroll
                for (int j = 0; j < 4; j++) {
                    int col = k0 + nt * 8 + colb + (j & 1);
                    if (col >= NS) sacc[nt][j] = -INFINITY;
                }
        }

        // ---- online softmax ----
        float ml0 = -INFINITY, ml1 = -INFINITY;
#pragma unroll
        for (int nt = 0; nt < 8; nt++) {
            ml0 = fmaxf(ml0, fmaxf(sacc[nt][0], sacc[nt][1]));
            ml1 = fmaxf(ml1, fmaxf(sacc[nt][2], sacc[nt][3]));
        }
        ml0 = fmaxf(ml0, __shfl_xor_sync(0xffffffffu, ml0, 1));
        ml0 = fmaxf(ml0, __shfl_xor_sync(0xffffffffu, ml0, 2));
        ml1 = fmaxf(ml1, __shfl_xor_sync(0xffffffffu, ml1, 1));
        ml1 = fmaxf(ml1, __shfl_xor_sync(0xffffffffu, ml1, 2));

        float mn0 = fmaxf(mrun[0], ml0), mn1 = fmaxf(mrun[1], ml1);
        float al0 = __expf(mrun[0] - mn0), al1 = __expf(mrun[1] - mn1);
        mrun[0] = mn0; mrun[1] = mn1;

        float rs0 = 0.f, rs1 = 0.f;
#pragma unroll
        for (int nt = 0; nt < 8; nt++) {
            float p00 = __expf(sacc[nt][0] - mn0);
            float p01 = __expf(sacc[nt][1] - mn0);
            float p10 = __expf(sacc[nt][2] - mn1);
            float p11 = __expf(sacc[nt][3] - mn1);
            rs0 += p00 + p01;
            rs1 += p10 + p11;
            __nv_bfloat16 h0, l0, h1, l1;
            bsplit(p00, h0, l0); bsplit(p01, h1, l1);
            uint32_t po = (uint32_t)(prow_lo * VSTB + (nt * 8 + colb) * 2);
            *(__nv_bfloat162*)(sm + OFF_PH + po) = __halves2bfloat162(h0, h1);
            *(__nv_bfloat162*)(sm + OFF_PL + po) = __halves2bfloat162(l0, l1);
            bsplit(p10, h0, l0); bsplit(p11, h1, l1);
            uint32_t po2 = po + 8 * VSTB;
            *(__nv_bfloat162*)(sm + OFF_PH + po2) = __halves2bfloat162(h0, h1);
            *(__nv_bfloat162*)(sm + OFF_PL + po2) = __halves2bfloat162(l0, l1);
        }
        rs0 += __shfl_xor_sync(0xffffffffu, rs0, 1);
        rs0 += __shfl_xor_sync(0xffffffffu, rs0, 2);
        rs1 += __shfl_xor_sync(0xffffffffu, rs1, 1);
        rs1 += __shfl_xor_sync(0xffffffffu, rs1, 2);
        lrun[0] = lrun[0] * al0 + rs0;
        lrun[1] = lrun[1] * al1 + rs1;

#pragma unroll
        for (int nt = 0; nt < 11; nt++) {
            acc_o[nt][0] *= al0; acc_o[nt][1] *= al0;
            acc_o[nt][2] *= al1; acc_o[nt][3] *= al1;
        }
        __syncwarp();

        // ---- O += P V (3-term split) ----
#pragma unroll
        for (int ks = 0; ks < 4; ks++) {
            uint32_t aph[4], apl[4];
            ldsm_x4(aph, smemu + OFF_PH + apoff + ks * 32);
            ldsm_x4(apl, smemu + OFF_PL + apoff + ks * 32);
            uint32_t vbh[24], vbl[24];
#pragma unroll
            for (int j = 0; j < 6; j++) {
                ldsm_x4(&vbh[j * 4], smemu + OFF_VH + vboff + j * 16 * VSTB + ks * 32);
                ldsm_x4(&vbl[j * 4], smemu + OFF_VL + vboff + j * 16 * VSTB + ks * 32);
            }
#pragma unroll
            for (int nt = 0; nt < 11; nt++) {
                mma_bf16(acc_o[nt], aph, &vbh[nt * 2]);
                mma_bf16(acc_o[nt], aph, &vbl[nt * 2]);
                mma_bf16(acc_o[nt], apl, &vbh[nt * 2]);
            }
        }
        __syncthreads();
    }

    // ---- epilogue: ctx fp32 ----
    const float inv0 = 1.f / lrun[0];
    const float inv1 = 1.f / lrun[1];
    const int gq0 = q0 + wm + (lane >> 2);
    const int gq1 = gq0 + 8;
    float* obase = g_ctx + (size_t)b * NS * NE + (size_t)h * ND;
#pragma unroll
    for (int nt = 0; nt < 11; nt++) {
        int col = nt * 8 + colb;
        if (gq0 < NS)
            *(float2*)(obase + (size_t)gq0 * NE + col) =
                make_float2(acc_o[nt][0] * inv0, acc_o[nt][1] * inv0);
        if (gq1 < NS)
            *(float2*)(obase + (size_t)gq1 * NE + col) =
                make_float2(acc_o[nt][2] * inv1, acc_o[nt][3] * inv1);
    }
}

// ---------------------------------------------------------------------------
// Launch
// ---------------------------------------------------------------------------
extern "C" void kernel_launch(void* const* d_in, const int* in_sizes, int n_in,
                              void* d_out, int out_size)
{
    const float* hidden = (const float*)d_in[0];
    const float* fcos   = (const float*)d_in[1];
    const float* fsin   = (const float*)d_in[2];
    const float* Wq     = (const float*)d_in[3];
    const float* bq     = (const float*)d_in[4];
    const float* Wk     = (const float*)d_in[5];
    const float* bk     = (const float*)d_in[6];
    const float* Wv     = (const float*)d_in[7];
    const float* bv     = (const float*)d_in[8];
    const float* Wo     = (const float*)d_in[9];
    const float* bo     = (const float*)d_in[10];
    float* out = (float*)d_out;

    float* ctxp;
    __nv_bfloat16 *qh, *ql, *kh, *kl, *vth, *vtl;
    cudaGetSymbolAddress((void**)&ctxp, g_ctx);
    cudaGetSymbolAddress((void**)&qh,  g_qh);
    cudaGetSymbolAddress((void**)&ql,  g_ql);
    cudaGetSymbolAddress((void**)&kh,  g_kh);
    cudaGetSymbolAddress((void**)&kl,  g_kl);
    cudaGetSymbolAddress((void**)&vth, g_vth);
    cudaGetSymbolAddress((void**)&vtl, g_vtl);

    static int smem_set = 0;
    if (!smem_set) {
        cudaFuncSetAttribute(gemm_hmma_kernel<0>,
                             cudaFuncAttributeMaxDynamicSharedMemorySize, GEMM_SMEM);
        cudaFuncSetAttribute(gemm_hmma_kernel<1>,
                             cudaFuncAttributeMaxDynamicSharedMemorySize, GEMM_SMEM);
        cudaFuncSetAttribute(gemm_hmma_kernel<2>,
                             cudaFuncAttributeMaxDynamicSharedMemorySize, GEMM_SMEM);
        cudaFuncSetAttribute(attn_hmma_kernel,
                             cudaFuncAttributeMaxDynamicSharedMemorySize, ATT_SMEM);
        smem_set = 1;
    }

    dim3 gemm_grid(NE / 128, (NM + 127) / 128);  // (11, 65)

    gemm_hmma_kernel<1><<<gemm_grid, 256, GEMM_SMEM>>>(
        hidden, Wq, bq, nullptr, qh, ql, fcos, fsin, NM);
    gemm_hmma_kernel<1><<<gemm_grid, 256, GEMM_SMEM>>>(
        hidden, Wk, bk, nullptr, kh, kl, fcos, fsin, NM);
    gemm_hmma_kernel<2><<<gemm_grid, 256, GEMM_SMEM>>>(
        hidden, Wv, bv, nullptr, vth, vtl, nullptr, nullptr, NM);

    dim3 attn_grid(17, NH, NB);
    attn_hmma_kernel<<<attn_grid, 128, ATT_SMEM>>>();

    gemm_hmma_kernel<0><<<gemm_grid, 256, GEMM_SMEM>>>(
        ctxp, Wo, bo, out, nullptr, nullptr, nullptr, nullptr, NM);
}

// round 7
// speedup vs baseline: 3.1714x; 1.0808x over previous
#include <cuda_runtime.h>
#include <cuda_bf16.h>
#include <math.h>
#include <stdint.h>

#define NB 8
#define NS 1025
#define NE 1408
#define NH 16
#define ND 88
#define NM (NB*NS)      // 8200
#define DPAD 96
#define QKROW (NH*DPAD) // 1536
#define SVT 1088        // padded token dim for V^T (17*64)
#define EE  (NE*NE)

// Persistent scratch (__device__ globals zero-initialized; padding regions
// never written -> stay zero, used as MMA zero-padding).
static __device__ __nv_bfloat16 g_ah[(size_t)NM * NE];
static __device__ __nv_bfloat16 g_al[(size_t)NM * NE];
static __device__ __nv_bfloat16 g_wh[(size_t)4 * EE];
static __device__ __nv_bfloat16 g_wl[(size_t)4 * EE];
static __device__ __nv_bfloat16 g_ch[(size_t)NM * NE];
static __device__ __nv_bfloat16 g_cl[(size_t)NM * NE];
static __device__ __nv_bfloat16 g_qh[(size_t)NM * QKROW];
static __device__ __nv_bfloat16 g_ql[(size_t)NM * QKROW];
static __device__ __nv_bfloat16 g_kh[(size_t)NM * QKROW];
static __device__ __nv_bfloat16 g_kl[(size_t)NM * QKROW];
static __device__ __nv_bfloat16 g_vth[(size_t)NB * NH * DPAD * SVT];
static __device__ __nv_bfloat16 g_vtl[(size_t)NB * NH * DPAD * SVT];

// ===========================================================================
// Helpers
// ===========================================================================
__device__ __forceinline__ uint32_t smem_to_u32(const void* p) {
    uint32_t a;
    asm("{ .reg .u64 t; cvta.to.shared.u64 t, %1; cvt.u32.u64 %0, t; }"
        : "=r"(a) : "l"(p));
    return a;
}
__device__ __forceinline__ void ldsm_x4(uint32_t* r, uint32_t addr) {
    asm volatile("ldmatrix.sync.aligned.m8n8.x4.shared.b16 {%0,%1,%2,%3}, [%4];"
                 : "=r"(r[0]), "=r"(r[1]), "=r"(r[2]), "=r"(r[3]) : "r"(addr));
}
__device__ __forceinline__ void mma_bf16(float* c, const uint32_t* a,
                                         const uint32_t* b) {
    asm volatile(
        "mma.sync.aligned.m16n8k16.row.col.f32.bf16.bf16.f32 "
        "{%0,%1,%2,%3}, {%4,%5,%6,%7}, {%8,%9}, {%0,%1,%2,%3};"
        : "+f"(c[0]), "+f"(c[1]), "+f"(c[2]), "+f"(c[3])
        : "r"(a[0]), "r"(a[1]), "r"(a[2]), "r"(a[3]), "r"(b[0]), "r"(b[1]));
}
__device__ __forceinline__ void cp16(uint32_t dst, const void* src) {
    asm volatile("cp.async.cg.shared.global [%0], [%1], 16;"
                 :: "r"(dst), "l"(__cvta_generic_to_global(src)));
}
#define CP_COMMIT() asm volatile("cp.async.commit_group;" ::: "memory")
#define CP_WAIT0()  asm volatile("cp.async.wait_group 0;" ::: "memory")
#define CP_WAIT1()  asm volatile("cp.async.wait_group 1;" ::: "memory")

__device__ __forceinline__ void bsplit(float x, __nv_bfloat16& h, __nv_bfloat16& l) {
    h = __float2bfloat16(x);
    l = __float2bfloat16(x - __bfloat162float(h));
}

// ===========================================================================
// Prep: split fp32 -> bf16 hi/lo (vectorized)
// ===========================================================================
__global__ void split_kernel(const float* __restrict__ in,
                             __nv_bfloat16* __restrict__ hi,
                             __nv_bfloat16* __restrict__ lo, int n4)
{
    int i = blockIdx.x * blockDim.x + threadIdx.x;
    if (i >= n4) return;
    float4 x = ((const float4*)in)[i];
    union { __nv_bfloat162 h2[2]; uint2 u; } H, L;
    __nv_bfloat162 h0 = __float22bfloat162_rn(make_float2(x.x, x.y));
    float2 f0 = __bfloat1622float2(h0);
    H.h2[0] = h0;
    L.h2[0] = __float22bfloat162_rn(make_float2(x.x - f0.x, x.y - f0.y));
    __nv_bfloat162 h1 = __float22bfloat162_rn(make_float2(x.z, x.w));
    float2 f1 = __bfloat1622float2(h1);
    H.h2[1] = h1;
    L.h2[1] = __float22bfloat162_rn(make_float2(x.z - f1.x, x.w - f1.y));
    ((uint2*)hi)[i] = H.u;
    ((uint2*)lo)[i] = L.u;
}

// ===========================================================================
// HMMA GEMM, split bf16 inputs (3 terms): C = A*W^T + bias
// A (hi/lo) [M,K] bf16, W (hi/lo) [N,K] bf16, K=1408.
// CTA 128x128, BK=32, 8 warps, cp.async 2-stage pipeline, zero conversions.
// MODE 0: fp32 out.  MODE 1: RoPE + bf16 hi/lo to padded [m][1536].
// MODE 2: bf16 hi/lo transposed to [b,h,96,1088].
// ===========================================================================
#define GK      NE
#define BKC     32
#define NCHUNK  (GK / BKC)    // 44
#define SROW    40
#define MAT_BYTES   (128 * SROW * 2)       // 10240
#define STAGE_BYTES (4 * MAT_BYTES)        // 40960
#define GEMM_SMEM   (2 * STAGE_BYTES)      // 81920

template<int MODE>
__global__ __launch_bounds__(256) void gemm_hmma_kernel(
    const __nv_bfloat16* __restrict__ Ah, const __nv_bfloat16* __restrict__ Al,
    const __nv_bfloat16* __restrict__ Wh, const __nv_bfloat16* __restrict__ Wl,
    const float* __restrict__ bias, float* __restrict__ C,
    __nv_bfloat16* __restrict__ Oh, __nv_bfloat16* __restrict__ Ol,
    const float* __restrict__ rcos, const float* __restrict__ rsin, int M)
{
    extern __shared__ char sm[];
    const uint32_t smemu = smem_to_u32(sm);
    const int tid  = threadIdx.x;
    const int wid  = tid >> 5;
    const int lane = tid & 31;
    const int bm = blockIdx.y * 128;
    const int bn = blockIdx.x * 128;
    const int wm = (wid >> 2) * 64;
    const int wn = (wid & 3) * 32;

    // cp.async load slots: per matrix 512 x 16B; thread does 2 per matrix
    int rowL[2], chL[2];
    int gaL[2];
#pragma unroll
    for (int i = 0; i < 2; i++) {
        int slot = tid + i * 256;
        rowL[i] = slot >> 2;
        chL[i]  = slot & 3;
        int ga = bm + rowL[i];
        gaL[i] = (ga < M) ? ga : (M - 1);
    }

    const uint32_t aoff =
        (uint32_t)((wm + ((lane >> 3) & 1) * 8 + (lane & 7)) * (SROW * 2)
                   + (lane >> 4) * 16);
    const uint32_t boff =
        (uint32_t)((wn + ((lane >> 4) << 3) + (lane & 7)) * (SROW * 2)
                   + ((lane >> 3) & 1) * 16);

    float acc[4][4][4];
#pragma unroll
    for (int mi = 0; mi < 4; mi++)
#pragma unroll
        for (int ni = 0; ni < 4; ni++)
#pragma unroll
            for (int j = 0; j < 4; j++) acc[mi][ni][j] = 0.f;

#define GEMM_LOAD(c_) do { \
    const int k0_ = (c_) * BKC; \
    const uint32_t sb_ = smemu + ((c_) & 1) * STAGE_BYTES; \
    _Pragma("unroll") \
    for (int i_ = 0; i_ < 2; i_++) { \
        uint32_t so_ = (uint32_t)(rowL[i_] * (SROW * 2) + chL[i_] * 16); \
        size_t ao_ = ((size_t)gaL[i_] * GK + k0_ + chL[i_] * 8) * 2; \
        cp16(sb_ + so_,                 (const char*)Ah + ao_); \
        cp16(sb_ + MAT_BYTES + so_,     (const char*)Al + ao_); \
        size_t bo_ = ((size_t)(bn + rowL[i_]) * GK + k0_ + chL[i_] * 8) * 2; \
        cp16(sb_ + 2 * MAT_BYTES + so_, (const char*)Wh + bo_); \
        cp16(sb_ + 3 * MAT_BYTES + so_, (const char*)Wl + bo_); \
    } \
} while (0)

    GEMM_LOAD(0);
    CP_COMMIT();

#pragma unroll 1
    for (int c = 0; c < NCHUNK; c++) {
        if (c + 1 < NCHUNK) {
            GEMM_LOAD(c + 1);
            CP_COMMIT();
            CP_WAIT1();
        } else {
            CP_WAIT0();
        }
        __syncthreads();

        const uint32_t base = smemu + (uint32_t)((c & 1) * STAGE_BYTES);
        const uint32_t aHi = base;
        const uint32_t aLo = base + MAT_BYTES;
        const uint32_t bHi = base + 2 * MAT_BYTES;
        const uint32_t bLo = base + 3 * MAT_BYTES;
#pragma unroll
        for (int ks = 0; ks < 2; ks++) {
            const uint32_t ksb = ks * 32;
            uint32_t ah[16], al[16], bh[8], bl[8];
#pragma unroll
            for (int mi = 0; mi < 4; mi++) {
                ldsm_x4(&ah[mi * 4], aHi + aoff + mi * 16 * (SROW * 2) + ksb);
                ldsm_x4(&al[mi * 4], aLo + aoff + mi * 16 * (SROW * 2) + ksb);
            }
            ldsm_x4(&bh[0], bHi + boff + ksb);
            ldsm_x4(&bh[4], bHi + boff + 16 * (SROW * 2) + ksb);
            ldsm_x4(&bl[0], bLo + boff + ksb);
            ldsm_x4(&bl[4], bLo + boff + 16 * (SROW * 2) + ksb);
#pragma unroll
            for (int mi = 0; mi < 4; mi++)
#pragma unroll
                for (int ni = 0; ni < 4; ni++) {
                    mma_bf16(acc[mi][ni], &ah[mi * 4], &bh[ni * 2]);
                    mma_bf16(acc[mi][ni], &ah[mi * 4], &bl[ni * 2]);
                    mma_bf16(acc[mi][ni], &al[mi * 4], &bh[ni * 2]);
                }
        }
        __syncthreads();
    }

    // ---- epilogue ----
    const int r0 = bm + wm + (lane >> 2);
    const int c0 = bn + wn + (lane & 3) * 2;
#pragma unroll
    for (int mi = 0; mi < 4; mi++) {
#pragma unroll
        for (int ni = 0; ni < 4; ni++) {
            const int gc = c0 + ni * 8;
            const float bx = bias[gc], by = bias[gc + 1];
            const int hh = gc / ND;
            const int dd = gc - hh * ND;
#pragma unroll
            for (int half = 0; half < 2; half++) {
                const int gr = r0 + mi * 16 + half * 8;
                if (gr >= M) continue;
                float xr = acc[mi][ni][2 * half + 0] + bx;
                float xi = acc[mi][ni][2 * half + 1] + by;
                if (MODE == 0) {
                    *(float2*)(C + (size_t)gr * NE + gc) = make_float2(xr, xi);
                } else if (MODE == 1) {
                    const int st = gr % NS;
                    const float cc = rcos[st * (ND / 2) + (dd >> 1)];
                    const float ss = rsin[st * (ND / 2) + (dd >> 1)];
                    float orr = xr * cc - xi * ss;
                    float oii = xr * ss + xi * cc;
                    __nv_bfloat16 h0, l0, h1, l1;
                    bsplit(orr, h0, l0);
                    bsplit(oii, h1, l1);
                    size_t off = (size_t)gr * QKROW + hh * DPAD + dd;
                    *(__nv_bfloat162*)(Oh + off) = __halves2bfloat162(h0, h1);
                    *(__nv_bfloat162*)(Ol + off) = __halves2bfloat162(l0, l1);
                } else {
                    const int bb = gr / NS;
                    const int st = gr - bb * NS;
                    size_t base2 = ((size_t)((bb * NH + hh) * DPAD) + dd) * SVT + st;
                    __nv_bfloat16 h0, l0, h1, l1;
                    bsplit(xr, h0, l0);
                    bsplit(xi, h1, l1);
                    Oh[base2]       = h0;
                    Ol[base2]       = l0;
                    Oh[base2 + SVT] = h1;
                    Ol[base2 + SVT] = l1;
                }
            }
        }
    }
}

// ===========================================================================
// HMMA flash attention, split bf16 (3 terms both GEMMs).
// BQ=64, BK=64, 4 warps; epilogue writes ctx as bf16 hi/lo for the Wo GEMM.
// ===========================================================================
#define KSTB 208
#define VSTB 144
#define OFF_KH 0
#define OFF_KL 13312
#define OFF_VH 26624
#define OFF_VL 40448
#define OFF_PH 54272
#define OFF_PL 63488
#define ATT_SMEM 72704

__global__ __launch_bounds__(128, 3) void attn_hmma_kernel()
{
    extern __shared__ char sm[];
    const uint32_t smemu = smem_to_u32(sm);
    const int tid  = threadIdx.x;
    const int wid  = tid >> 5;
    const int lane = tid & 31;
    const int wm   = wid * 16;

    const int qt = blockIdx.x, h = blockIdx.y, b = blockIdx.z;
    const int q0 = qt * 64;

    const char* qh_base = (const char*)(g_qh + (size_t)b * NS * QKROW + h * DPAD);
    const char* ql_base = (const char*)(g_ql + (size_t)b * NS * QKROW + h * DPAD);
    const char* kh_base = (const char*)(g_kh + (size_t)b * NS * QKROW + h * DPAD);
    const char* kl_base = (const char*)(g_kl + (size_t)b * NS * QKROW + h * DPAD);
    const char* vh_base = (const char*)(g_vth + (size_t)(b * NH + h) * DPAD * SVT);
    const char* vl_base = (const char*)(g_vtl + (size_t)(b * NH + h) * DPAD * SVT);

    // ---- stage Q via K buffers, build register fragments ----
    for (int i = tid; i < 768; i += 128) {
        int row = i / 12, ch = i % 12;
        int tok = q0 + row; if (tok > NS - 1) tok = NS - 1;
        size_t gb = (size_t)tok * (QKROW * 2) + ch * 16;
        cp16(smemu + OFF_KH + row * KSTB + ch * 16, qh_base + gb);
        cp16(smemu + OFF_KL + row * KSTB + ch * 16, ql_base + gb);
    }
    CP_COMMIT(); CP_WAIT0();
    __syncthreads();

    const uint32_t aoffQ = (uint32_t)((wm + ((lane >> 3) & 1) * 8 + (lane & 7)) * KSTB
                                      + (lane >> 4) * 16);
    uint32_t qhf[6][4], qlf[6][4];
#pragma unroll
    for (int ks = 0; ks < 6; ks++) {
        ldsm_x4(qhf[ks], smemu + OFF_KH + aoffQ + ks * 32);
        ldsm_x4(qlf[ks], smemu + OFF_KL + aoffQ + ks * 32);
    }
    __syncthreads();

    float acc_o[11][4];
#pragma unroll
    for (int nt = 0; nt < 11; nt++)
#pragma unroll
        for (int j = 0; j < 4; j++) acc_o[nt][j] = 0.f;
    float mrun[2] = {-INFINITY, -INFINITY};
    float lrun[2] = {0.f, 0.f};

    const float scale = 0.10660035817780521f;
    const uint32_t kboff = (uint32_t)((((lane >> 4) << 3) + (lane & 7)) * KSTB
                                      + ((lane >> 3) & 1) * 16);
    const uint32_t vboff = (uint32_t)((((lane >> 4) << 3) + (lane & 7)) * VSTB
                                      + ((lane >> 3) & 1) * 16);
    const uint32_t apoff = (uint32_t)((wm + ((lane >> 3) & 1) * 8 + (lane & 7)) * VSTB
                                      + (lane >> 4) * 16);
    const int colb = (lane & 3) * 2;
    const int prow_lo = wm + (lane >> 2);

#pragma unroll 1
    for (int kt = 0; kt < 17; kt++) {
        const int k0 = kt * 64;

        for (int i = tid; i < 768; i += 128) {
            int rk = i / 12, ck = i % 12;
            int tok = k0 + rk; if (tok > NS - 1) tok = NS - 1;
            size_t gk = (size_t)tok * (QKROW * 2) + ck * 16;
            cp16(smemu + OFF_KH + rk * KSTB + ck * 16, kh_base + gk);
            cp16(smemu + OFF_KL + rk * KSTB + ck * 16, kl_base + gk);
            int rv = i / 8, cv = i % 8;
            size_t gv = (size_t)rv * (SVT * 2) + k0 * 2 + cv * 16;
            cp16(smemu + OFF_VH + rv * VSTB + cv * 16, vh_base + gv);
            cp16(smemu + OFF_VL + rv * VSTB + cv * 16, vl_base + gv);
        }
        CP_COMMIT(); CP_WAIT0();
        __syncthreads();

        // ---- S = Q K^T ----
        float sacc[8][4];
#pragma unroll
        for (int nt = 0; nt < 8; nt++)
#pragma unroll
            for (int j = 0; j < 4; j++) sacc[nt][j] = 0.f;

#pragma unroll
        for (int ks = 0; ks < 6; ks++) {
            uint32_t kbh[16], kbl[16];
#pragma unroll
            for (int j = 0; j < 4; j++) {
                ldsm_x4(&kbh[j * 4], smemu + OFF_KH + kboff + j * 16 * KSTB + ks * 32);
                ldsm_x4(&kbl[j * 4], smemu + OFF_KL + kboff + j * 16 * KSTB + ks * 32);
            }
#pragma unroll
            for (int nt = 0; nt < 8; nt++) {
                mma_bf16(sacc[nt], qhf[ks], &kbh[nt * 2]);
                mma_bf16(sacc[nt], qhf[ks], &kbl[nt * 2]);
                mma_bf16(sacc[nt], qlf[ks], &kbh[nt * 2]);
            }
        }

#pragma unroll
        for (int nt = 0; nt < 8; nt++)
#pragma unroll
            for (int j = 0; j < 4; j++) sacc[nt][j] *= scale;
        if (k0 + 64 > NS) {
#pragma unroll
            for (int nt = 0; nt < 8; nt++)
#pragma unroll
                for (int j = 0; j < 4; j++) {
                    int col = k0 + nt * 8 + colb + (j & 1);
                    if (col >= NS) sacc[nt][j] = -INFINITY;
                }
        }

        // ---- online softmax ----
        float ml0 = -INFINITY, ml1 = -INFINITY;
#pragma unroll
        for (int nt = 0; nt < 8; nt++) {
            ml0 = fmaxf(ml0, fmaxf(sacc[nt][0], sacc[nt][1]));
            ml1 = fmaxf(ml1, fmaxf(sacc[nt][2], sacc[nt][3]));
        }
        ml0 = fmaxf(ml0, __shfl_xor_sync(0xffffffffu, ml0, 1));
        ml0 = fmaxf(ml0, __shfl_xor_sync(0xffffffffu, ml0, 2));
        ml1 = fmaxf(ml1, __shfl_xor_sync(0xffffffffu, ml1, 1));
        ml1 = fmaxf(ml1, __shfl_xor_sync(0xffffffffu, ml1, 2));

        float mn0 = fmaxf(mrun[0], ml0), mn1 = fmaxf(mrun[1], ml1);
        float al0 = __expf(mrun[0] - mn0), al1 = __expf(mrun[1] - mn1);
        mrun[0] = mn0; mrun[1] = mn1;

        float rs0 = 0.f, rs1 = 0.f;
#pragma unroll
        for (int nt = 0; nt < 8; nt++) {
            float p00 = __expf(sacc[nt][0] - mn0);
            float p01 = __expf(sacc[nt][1] - mn0);
            float p10 = __expf(sacc[nt][2] - mn1);
            float p11 = __expf(sacc[nt][3] - mn1);
            rs0 += p00 + p01;
            rs1 += p10 + p11;
            __nv_bfloat16 h0, l0, h1, l1;
            bsplit(p00, h0, l0); bsplit(p01, h1, l1);
            uint32_t po = (uint32_t)(prow_lo * VSTB + (nt * 8 + colb) * 2);
            *(__nv_bfloat162*)(sm + OFF_PH + po) = __halves2bfloat162(h0, h1);
            *(__nv_bfloat162*)(sm + OFF_PL + po) = __halves2bfloat162(l0, l1);
            bsplit(p10, h0, l0); bsplit(p11, h1, l1);
            uint32_t po2 = po + 8 * VSTB;
            *(__nv_bfloat162*)(sm + OFF_PH + po2) = __halves2bfloat162(h0, h1);
            *(__nv_bfloat162*)(sm + OFF_PL + po2) = __halves2bfloat162(l0, l1);
        }
        rs0 += __shfl_xor_sync(0xffffffffu, rs0, 1);
        rs0 += __shfl_xor_sync(0xffffffffu, rs0, 2);
        rs1 += __shfl_xor_sync(0xffffffffu, rs1, 1);
        rs1 += __shfl_xor_sync(0xffffffffu, rs1, 2);
        lrun[0] = lrun[0] * al0 + rs0;
        lrun[1] = lrun[1] * al1 + rs1;

#pragma unroll
        for (int nt = 0; nt < 11; nt++) {
            acc_o[nt][0] *= al0; acc_o[nt][1] *= al0;
            acc_o[nt][2] *= al1; acc_o[nt][3] *= al1;
        }
        __syncwarp();

        // ---- O += P V ----
#pragma unroll
        for (int ks = 0; ks < 4; ks++) {
            uint32_t aph[4], apl[4];
            ldsm_x4(aph, smemu + OFF_PH + apoff + ks * 32);
            ldsm_x4(apl, smemu + OFF_PL + apoff + ks * 32);
            uint32_t vbh[24], vbl[24];
#pragma unroll
            for (int j = 0; j < 6; j++) {
                ldsm_x4(&vbh[j * 4], smemu + OFF_VH + vboff + j * 16 * VSTB + ks * 32);
                ldsm_x4(&vbl[j * 4], smemu + OFF_VL + vboff + j * 16 * VSTB + ks * 32);
            }
#pragma unroll
            for (int nt = 0; nt < 11; nt++) {
                mma_bf16(acc_o[nt], aph, &vbh[nt * 2]);
                mma_bf16(acc_o[nt], aph, &vbl[nt * 2]);
                mma_bf16(acc_o[nt], apl, &vbh[nt * 2]);
            }
        }
        __syncthreads();
    }

    // ---- epilogue: ctx as bf16 hi/lo (feeds Wo GEMM directly) ----
    const float inv0 = 1.f / lrun[0];
    const float inv1 = 1.f / lrun[1];
    const int gq0 = q0 + wm + (lane >> 2);
    const int gq1 = gq0 + 8;
    const size_t ob = (size_t)b * NS * NE + (size_t)h * ND;
#pragma unroll
    for (int nt = 0; nt < 11; nt++) {
        int col = nt * 8 + colb;
        __nv_bfloat16 h0, l0, h1, l1;
        if (gq0 < NS) {
            bsplit(acc_o[nt][0] * inv0, h0, l0);
            bsplit(acc_o[nt][1] * inv0, h1, l1);
            size_t off = ob + (size_t)gq0 * NE + col;
            *(__nv_bfloat162*)(g_ch + off) = __halves2bfloat162(h0, h1);
            *(__nv_bfloat162*)(g_cl + off) = __halves2bfloat162(l0, l1);
        }
        if (gq1 < NS) {
            bsplit(acc_o[nt][2] * inv1, h0, l0);
            bsplit(acc_o[nt][3] * inv1, h1, l1);
            size_t off = ob + (size_t)gq1 * NE + col;
            *(__nv_bfloat162*)(g_ch + off) = __halves2bfloat162(h0, h1);
            *(__nv_bfloat162*)(g_cl + off) = __halves2bfloat162(l0, l1);
        }
    }
}

// ---------------------------------------------------------------------------
// Launch
// ---------------------------------------------------------------------------
extern "C" void kernel_launch(void* const* d_in, const int* in_sizes, int n_in,
                              void* d_out, int out_size)
{
    const float* hidden = (const float*)d_in[0];
    const float* fcos   = (const float*)d_in[1];
    const float* fsin   = (const float*)d_in[2];
    const float* Wq     = (const float*)d_in[3];
    const float* bq     = (const float*)d_in[4];
    const float* Wk     = (const float*)d_in[5];
    const float* bk     = (const float*)d_in[6];
    const float* Wv     = (const float*)d_in[7];
    const float* bv     = (const float*)d_in[8];
    const float* Wo     = (const float*)d_in[9];
    const float* bo     = (const float*)d_in[10];
    float* out = (float*)d_out;

    __nv_bfloat16 *ah, *al, *wh, *wl, *ch, *cl, *qh, *ql, *kh, *kl, *vth, *vtl;
    cudaGetSymbolAddress((void**)&ah,  g_ah);
    cudaGetSymbolAddress((void**)&al,  g_al);
    cudaGetSymbolAddress((void**)&wh,  g_wh);
    cudaGetSymbolAddress((void**)&wl,  g_wl);
    cudaGetSymbolAddress((void**)&ch,  g_ch);
    cudaGetSymbolAddress((void**)&cl,  g_cl);
    cudaGetSymbolAddress((void**)&qh,  g_qh);
    cudaGetSymbolAddress((void**)&ql,  g_ql);
    cudaGetSymbolAddress((void**)&kh,  g_kh);
    cudaGetSymbolAddress((void**)&kl,  g_kl);
    cudaGetSymbolAddress((void**)&vth, g_vth);
    cudaGetSymbolAddress((void**)&vtl, g_vtl);

    static int smem_set = 0;
    if (!smem_set) {
        cudaFuncSetAttribute(gemm_hmma_kernel<0>,
                             cudaFuncAttributeMaxDynamicSharedMemorySize, GEMM_SMEM);
        cudaFuncSetAttribute(gemm_hmma_kernel<1>,
                             cudaFuncAttributeMaxDynamicSharedMemorySize, GEMM_SMEM);
        cudaFuncSetAttribute(gemm_hmma_kernel<2>,
                             cudaFuncAttributeMaxDynamicSharedMemorySize, GEMM_SMEM);
        cudaFuncSetAttribute(attn_hmma_kernel,
                             cudaFuncAttributeMaxDynamicSharedMemorySize, ATT_SMEM);
        smem_set = 1;
    }

    // ---- prep: split fp32 -> bf16 hi/lo ----
    const int nA4 = NM * NE / 4;       // 2,886,400
    const int nW4 = EE / 4;            // 495,616
    split_kernel<<<(nA4 + 255) / 256, 256>>>(hidden, ah, al, nA4);
    split_kernel<<<(nW4 + 255) / 256, 256>>>(Wq, wh + 0 * (size_t)EE, wl + 0 * (size_t)EE, nW4);
    split_kernel<<<(nW4 + 255) / 256, 256>>>(Wk, wh + 1 * (size_t)EE, wl + 1 * (size_t)EE, nW4);
    split_kernel<<<(nW4 + 255) / 256, 256>>>(Wv, wh + 2 * (size_t)EE, wl + 2 * (size_t)EE, nW4);
    split_kernel<<<(nW4 + 255) / 256, 256>>>(Wo, wh + 3 * (size_t)EE, wl + 3 * (size_t)EE, nW4);

    dim3 gemm_grid(NE / 128, (NM + 127) / 128);  // (11, 65)

    gemm_hmma_kernel<1><<<gemm_grid, 256, GEMM_SMEM>>>(
        ah, al, wh + 0 * (size_t)EE, wl + 0 * (size_t)EE, bq, nullptr,
        qh, ql, fcos, fsin, NM);
    gemm_hmma_kernel<1><<<gemm_grid, 256, GEMM_SMEM>>>(
        ah, al, wh + 1 * (size_t)EE, wl + 1 * (size_t)EE, bk, nullptr,
        kh, kl, fcos, fsin, NM);
    gemm_hmma_kernel<2><<<gemm_grid, 256, GEMM_SMEM>>>(
        ah, al, wh + 2 * (size_t)EE, wl + 2 * (size_t)EE, bv, nullptr,
        vth, vtl, nullptr, nullptr, NM);

    dim3 attn_grid(17, NH, NB);
    attn_hmma_kernel<<<attn_grid, 128, ATT_SMEM>>>();

    gemm_hmma_kernel<0><<<gemm_grid, 256, GEMM_SMEM>>>(
        ch, cl, wh + 3 * (size_t)EE, wl + 3 * (size_t)EE, bo, out,
        nullptr, nullptr, nullptr, nullptr, NM);
}